// round 1
// baseline (speedup 1.0000x reference)
#include <cuda_runtime.h>

#define N_NODES 100000
#define N_EDGES 1600000
#define D 128
#define K2 256

// ---------------- scratch (device globals; no allocation allowed) ----------
__device__ int   g_deg[N_NODES];
__device__ int   g_off[N_NODES + 1];
__device__ int   g_cursor[N_NODES];
__device__ int   g_srcs[N_EDGES];
__device__ float g_ahn[(size_t)N_NODES * D];   // normalized aggregated features

// ---------------- small setup kernels ---------------------------------------
__global__ void k_zero_deg() {
    int i = blockIdx.x * blockDim.x + threadIdx.x;
    if (i < N_NODES) g_deg[i] = 0;
}

__global__ void k_count(const int* __restrict__ dst) {
    int e = blockIdx.x * blockDim.x + threadIdx.x;
    if (e < N_EDGES) atomicAdd(&g_deg[dst[e]], 1);
}

// single-block exclusive scan of g_deg -> g_off (and g_cursor copy)
__global__ void k_scan() {
    __shared__ int sums[1024];
    const int n = N_NODES;
    int tid = threadIdx.x;
    const int chunk = (n + 1023) / 1024;
    int base = tid * chunk;
    int s = 0;
    for (int i = 0; i < chunk; i++) {
        int idx = base + i;
        if (idx < n) s += g_deg[idx];
    }
    sums[tid] = s;
    __syncthreads();
    for (int off = 1; off < 1024; off <<= 1) {
        int v = (tid >= off) ? sums[tid - off] : 0;
        __syncthreads();
        sums[tid] += v;
        __syncthreads();
    }
    int run = (tid == 0) ? 0 : sums[tid - 1];
    for (int i = 0; i < chunk; i++) {
        int idx = base + i;
        if (idx < n) {
            g_off[idx] = run;
            g_cursor[idx] = run;
            run += g_deg[idx];
        }
    }
    if (tid == 1023) g_off[n] = sums[1023];
}

__global__ void k_scatter(const int* __restrict__ src, const int* __restrict__ dst) {
    int e = blockIdx.x * blockDim.x + threadIdx.x;
    if (e < N_EDGES) {
        int p = atomicAdd(&g_cursor[dst[e]], 1);
        g_srcs[p] = src[e];
    }
}

// ---------------- aggregation: one warp per dst node ------------------------
__global__ void k_aggregate(const float* __restrict__ h) {
    int warp = (blockIdx.x * blockDim.x + threadIdx.x) >> 5;
    int lane = threadIdx.x & 31;
    if (warp >= N_NODES) return;
    int beg = g_off[warp];
    int end = g_off[warp + 1];
    const float4* h4 = (const float4*)h;
    float4 acc = make_float4(0.f, 0.f, 0.f, 0.f);
    int e = beg;
    int s_next = (e < end) ? g_srcs[e] : 0;
    for (; e < end; ) {
        int s = s_next;
        ++e;
        if (e < end) s_next = g_srcs[e];
        float4 v = __ldg(&h4[(size_t)s * 32 + lane]);
        acc.x += v.x; acc.y += v.y; acc.z += v.z; acc.w += v.w;
    }
    float norm = (end > beg) ? 1.0f / (float)(end - beg) : 0.0f;
    acc.x *= norm; acc.y *= norm; acc.z *= norm; acc.w *= norm;
    ((float4*)g_ahn)[(size_t)warp * 32 + lane] = acc;
}

// ---------------- fused GEMM (cat @ W^T + b) + LayerNorm + ReLU --------------
// Block tile: 256 rows x 128 cols, 512 threads, 8x8 per thread.
// Full W kept k-major in shared (loaded once per block).
#define MT 256
#define NT 128
#define KT 32
#define ASTRIDE (MT + 4)   // 260
#define BSTRIDE (NT + 4)   // 132

__global__ void __launch_bounds__(512, 1)
k_gemm_ln(const float* __restrict__ h,
          const float* __restrict__ W,
          const float* __restrict__ bias,
          const float* __restrict__ gamma,
          const float* __restrict__ beta,
          float* __restrict__ out)
{
    extern __shared__ float smem[];
    float* As = smem;                       // [KT][ASTRIDE]
    float* Bs = smem + KT * ASTRIDE;        // [K2][BSTRIDE]

    int tid = threadIdx.x;
    int tx = tid & 15;    // n-group: cols tx*8 .. tx*8+7
    int ty = tid >> 4;    // m-group: rows ty*8 .. ty*8+7
    int row0 = blockIdx.x * MT;

    // ---- stage full W transposed: Bs[k][n] = W[n][k] ----
    {
        const float4* W4 = (const float4*)W;
        int kc = tid >> 3;   // 0..63  (k float4 chunk)
        int nb = tid & 7;    // n base
#pragma unroll
        for (int q = 0; q < 16; q++) {
            int n = nb + 8 * q;
            float4 v = W4[n * 64 + kc];
            int kk = kc * 4;
            Bs[(kk + 0) * BSTRIDE + n] = v.x;
            Bs[(kk + 1) * BSTRIDE + n] = v.y;
            Bs[(kk + 2) * BSTRIDE + n] = v.z;
            Bs[(kk + 3) * BSTRIDE + n] = v.w;
        }
    }

    // per-thread column params
    float gam[8], bet[8], bvec[8];
#pragma unroll
    for (int j = 0; j < 8; j++) {
        int c = tx * 8 + j;
        gam[j] = gamma[c];
        bet[j] = beta[c];
        bvec[j] = bias[c];
    }

    float acc[8][8];
#pragma unroll
    for (int i = 0; i < 8; i++)
#pragma unroll
        for (int j = 0; j < 8; j++) acc[i][j] = 0.f;

    const float4* h4 = (const float4*)h;
    const float4* a4 = (const float4*)g_ahn;

    for (int kb = 0; kb < K2; kb += KT) {
        __syncthreads();   // protect As (prev iter reads) / Bs (first iter writes)
        // stage A tile transposed: As[kk][m] = A[row0+m][kb+kk]
        {
            int kc = tid & 7;    // float4 chunk within KT
            int mb = tid >> 3;   // 0..63
#pragma unroll
            for (int q = 0; q < 4; q++) {
                int m = mb + 64 * q;
                int row = row0 + m;
                if (row >= N_NODES) row = N_NODES - 1;   // clamp (unused rows)
                float4 v;
                if (kb < D) v = h4[(size_t)row * 32 + (kb >> 2) + kc];
                else        v = a4[(size_t)row * 32 + ((kb - D) >> 2) + kc];
                int kk = kc * 4;
                As[(kk + 0) * ASTRIDE + m] = v.x;
                As[(kk + 1) * ASTRIDE + m] = v.y;
                As[(kk + 2) * ASTRIDE + m] = v.z;
                As[(kk + 3) * ASTRIDE + m] = v.w;
            }
        }
        __syncthreads();

#pragma unroll 4
        for (int k = 0; k < KT; k++) {
            const float* brow = &Bs[(kb + k) * BSTRIDE + (tx << 3)];
            float4 b0 = *(const float4*)brow;
            float4 b1 = *(const float4*)(brow + 4);
            const float* arow = &As[k * ASTRIDE + (ty << 3)];
            float4 a0 = *(const float4*)arow;
            float4 a1 = *(const float4*)(arow + 4);
            float av[8] = {a0.x, a0.y, a0.z, a0.w, a1.x, a1.y, a1.z, a1.w};
            float bv[8] = {b0.x, b0.y, b0.z, b0.w, b1.x, b1.y, b1.z, b1.w};
#pragma unroll
            for (int i = 0; i < 8; i++)
#pragma unroll
                for (int j = 0; j < 8; j++)
                    acc[i][j] = fmaf(av[i], bv[j], acc[i][j]);
        }
    }

    // ---- epilogue: bias + LayerNorm + ReLU, row-wise (128 cols over 16 lanes)
#pragma unroll
    for (int i = 0; i < 8; i++) {
        float s = 0.f;
#pragma unroll
        for (int j = 0; j < 8; j++) {
            acc[i][j] += bvec[j];
            s += acc[i][j];
        }
#pragma unroll
        for (int o = 8; o >= 1; o >>= 1)
            s += __shfl_xor_sync(0xffffffffu, s, o);
        float mu = s * (1.0f / 128.0f);

        float vs = 0.f;
#pragma unroll
        for (int j = 0; j < 8; j++) {
            float dlt = acc[i][j] - mu;
            vs += dlt * dlt;
        }
#pragma unroll
        for (int o = 8; o >= 1; o >>= 1)
            vs += __shfl_xor_sync(0xffffffffu, vs, o);
        float inv = rsqrtf(vs * (1.0f / 128.0f) + 1e-5f);

        int row = row0 + ty * 8 + i;
        if (row < N_NODES) {
            float o8[8];
#pragma unroll
            for (int j = 0; j < 8; j++) {
                float v = (acc[i][j] - mu) * inv * gam[j] + bet[j];
                o8[j] = v > 0.f ? v : 0.f;
            }
            float4* dst4 = (float4*)&out[(size_t)row * 128 + tx * 8];
            dst4[0] = make_float4(o8[0], o8[1], o8[2], o8[3]);
            dst4[1] = make_float4(o8[4], o8[5], o8[6], o8[7]);
        }
    }
}

// ---------------- launcher ---------------------------------------------------
extern "C" void kernel_launch(void* const* d_in, const int* in_sizes, int n_in,
                              void* d_out, int out_size) {
    const float* h     = (const float*)d_in[0];
    const float* W     = (const float*)d_in[1];
    const float* b     = (const float*)d_in[2];
    const float* gamma = (const float*)d_in[3];
    const float* beta  = (const float*)d_in[4];
    const int*   src   = (const int*)d_in[5];
    const int*   dst   = (const int*)d_in[6];
    float* out = (float*)d_out;

    k_zero_deg<<<(N_NODES + 255) / 256, 256>>>();
    k_count<<<(N_EDGES + 255) / 256, 256>>>(dst);
    k_scan<<<1, 1024>>>();
    k_scatter<<<(N_EDGES + 255) / 256, 256>>>(src, dst);
    k_aggregate<<<(N_NODES * 32 + 255) / 256, 256>>>(h);

    const size_t SMEM = (size_t)(KT * ASTRIDE + K2 * BSTRIDE) * sizeof(float);
    cudaFuncSetAttribute(k_gemm_ln, cudaFuncAttributeMaxDynamicSharedMemorySize,
                         (int)SMEM);
    k_gemm_ln<<<(N_NODES + MT - 1) / MT, 512, SMEM>>>(h, W, b, gamma, beta, out);
}